// round 1
// baseline (speedup 1.0000x reference)
#include <cuda_runtime.h>
#include <cuda_bf16.h>
#include <cstdint>

// Detector post-process:
//   xy = box[..,0:2] + prior[..,0:2]; wh = box[..,2:4] * prior[..,2:4]
//   corners = [xy - wh/2, xy + wh/2] / feat_size
//   scores = conf * class_score; prob = max_c, idx = argmax_c (first occurrence)
//   mask = prob > 0.5 -> zero out corners/prob where masked
//
// Inputs (metadata order):
//   d_in[0] box          float32  (N, HW, A, 4)   = 2,621,440
//   d_in[1] box_conf     float32  (N, HW, A, 1)   =   655,360
//   d_in[2] class_score  float32  (N, HW, A, 80)  = 52,428,800
//   d_in[3] prior        float32  (HW, A, 4)      =    81,920
//   d_in[4] feat_size    scalar (int32 or float32), value 64
//
// Output (flat float32):
//   [0, 4B)  box_out   (B = n_boxes = 655,360)
//   [4B, 5B) probs_out
//   [5B, 6B) class_index (stored as exact small-int floats)

#ifndef THRESHOLD
#define THRESHOLD 0.5f
#endif

__global__ __launch_bounds__(256) void detector_kernel(
    const float4* __restrict__ box,        // [B] of float4
    const float*  __restrict__ conf,       // [B]
    const float4* __restrict__ score4,     // [B*20] of float4 (80 floats per box)
    const float4* __restrict__ prior,      // [priorMod] of float4
    const unsigned* __restrict__ feat_raw, // scalar
    float4* __restrict__ box_out,          // [B]
    float*  __restrict__ probs_out,        // [B]
    float*  __restrict__ cls_out,          // [B]
    int n_boxes, int prior_mod)
{
    int i = blockIdx.x * blockDim.x + threadIdx.x;
    if (i >= n_boxes) return;

    // feat_size may arrive as int32 or float32 bits; decode robustly.
    unsigned fb = *feat_raw;
    float feat = (fb < 0x01000000u) ? (float)fb : __uint_as_float(fb);
    float inv_feat = 1.0f / feat;   // 1/64 is exact in fp32

    // ---- argmax over 80 classes of conf*score (first-occurrence ties) ----
    float c = conf[i];
    const float4* s = score4 + (size_t)i * 20;
    float best = -3.402823466e+38f;
    int bidx = 0;
    #pragma unroll
    for (int j = 0; j < 20; j++) {
        float4 v = s[j];
        float p0 = c * v.x, p1 = c * v.y, p2 = c * v.z, p3 = c * v.w;
        int base = j * 4;
        if (p0 > best) { best = p0; bidx = base;     }
        if (p1 > best) { best = p1; bidx = base + 1; }
        if (p2 > best) { best = p2; bidx = base + 2; }
        if (p3 > best) { best = p3; bidx = base + 3; }
    }

    // ---- box decode ----
    float4 b = box[i];
    float4 p = prior[i % prior_mod];
    float cx = b.x + p.x;
    float cy = b.y + p.y;
    float hw = 0.5f * (b.z * p.z);
    float hh = 0.5f * (b.w * p.w);

    float4 corners;
    corners.x = (cx - hw) * inv_feat;
    corners.y = (cy - hh) * inv_feat;
    corners.z = (cx + hw) * inv_feat;
    corners.w = (cy + hh) * inv_feat;

    bool m = best > THRESHOLD;
    box_out[i]   = m ? corners : make_float4(0.f, 0.f, 0.f, 0.f);
    probs_out[i] = m ? best : 0.0f;
    cls_out[i]   = (float)bidx;   // class_index, exact in fp32 (< 80)
}

extern "C" void kernel_launch(void* const* d_in, const int* in_sizes, int n_in,
                              void* d_out, int out_size)
{
    const float4*   box    = (const float4*)d_in[0];
    const float*    conf   = (const float*)d_in[1];
    const float4*   score4 = (const float4*)d_in[2];
    const float4*   prior  = (const float4*)d_in[3];
    const unsigned* feat   = (const unsigned*)d_in[4];

    int n_boxes   = in_sizes[1];       // box_confidence element count = N*HW*A
    int prior_mod = in_sizes[3] / 4;   // HW*A

    float* out       = (float*)d_out;
    float4* box_out  = (float4*)out;                       // n_boxes * 4 floats
    float*  probs    = out + (size_t)n_boxes * 4;          // n_boxes floats
    float*  cls      = out + (size_t)n_boxes * 5;          // n_boxes floats

    int threads = 256;
    int blocks = (n_boxes + threads - 1) / threads;
    detector_kernel<<<blocks, threads>>>(box, conf, score4, prior, feat,
                                         box_out, probs, cls,
                                         n_boxes, prior_mod);
}

// round 2
// speedup vs baseline: 1.3090x; 1.3090x over previous
#include <cuda_runtime.h>
#include <cuda_bf16.h>
#include <cstdint>

// Detector post-process, SMEM-staged for coalescing.
//
// Inputs (metadata order):
//   d_in[0] box          float32  (N, HW, A, 4)
//   d_in[1] box_conf     float32  (N, HW, A, 1)
//   d_in[2] class_score  float32  (N, HW, A, 80)
//   d_in[3] prior        float32  (HW, A, 4)
//   d_in[4] feat_size    scalar
//
// Output (flat float32): [box_out (B*4) | probs (B) | class_index (B)]

#ifndef THRESHOLD
#define THRESHOLD 0.5f
#endif

#define TB 128          // boxes (and threads) per block
#define F4_PER_BOX 20   // 80 floats
#define PAD_F4 21       // padded stride in float4 (84 words -> conflict-free LDS)

__global__ __launch_bounds__(TB) void detector_kernel(
    const float4* __restrict__ box,        // [B]
    const float*  __restrict__ conf,       // [B]
    const float4* __restrict__ score4,     // [B*20]
    const float4* __restrict__ prior,      // [prior_mod]
    const unsigned* __restrict__ feat_raw, // scalar
    float4* __restrict__ box_out,          // [B]
    float*  __restrict__ probs_out,        // [B]
    float*  __restrict__ cls_out,          // [B]
    int n_boxes, int prior_mod)
{
    __shared__ float4 s4[TB * PAD_F4];     // 43008 bytes

    const int t = threadIdx.x;
    const int tile_base = blockIdx.x * TB;         // first box of this tile
    const int i = tile_base + t;                   // this thread's box

    // ---- cooperative coalesced load of the tile's scores ----
    // tile source: 2560 contiguous float4; thread t copies k*TB + t.
    const float4* gsrc = score4 + (size_t)tile_base * F4_PER_BOX;
    const int tile_f4 = TB * F4_PER_BOX;
    #pragma unroll
    for (int k = 0; k < F4_PER_BOX; k++) {
        int g = k * TB + t;
        // guard only matters for a ragged tail tile
        if (tile_base * F4_PER_BOX + g < (size_t)n_boxes * F4_PER_BOX && g < tile_f4) {
            int b = g / F4_PER_BOX;
            int s = g - b * F4_PER_BOX;
            s4[b * PAD_F4 + s] = gsrc[g];
        }
    }
    __syncthreads();

    if (i >= n_boxes) return;

    // feat_size may arrive as int32 or float32 bits; decode robustly.
    unsigned fb = *feat_raw;
    float feat = (fb < 0x01000000u) ? (float)fb : __uint_as_float(fb);
    float inv_feat = 1.0f / feat;

    // ---- argmax over 80 classes of conf*score (first-occurrence ties) ----
    float c = conf[i];
    const float4* s = s4 + t * PAD_F4;
    float best = -3.402823466e+38f;
    int bidx = 0;
    #pragma unroll
    for (int j = 0; j < F4_PER_BOX; j++) {
        float4 v = s[j];
        float p0 = c * v.x, p1 = c * v.y, p2 = c * v.z, p3 = c * v.w;
        int base = j * 4;
        if (p0 > best) { best = p0; bidx = base;     }
        if (p1 > best) { best = p1; bidx = base + 1; }
        if (p2 > best) { best = p2; bidx = base + 2; }
        if (p3 > best) { best = p3; bidx = base + 3; }
    }

    // ---- box decode ----
    float4 b = box[i];
    float4 p = prior[i % prior_mod];
    float cx = b.x + p.x;
    float cy = b.y + p.y;
    float hw = 0.5f * (b.z * p.z);
    float hh = 0.5f * (b.w * p.w);

    float4 corners;
    corners.x = (cx - hw) * inv_feat;
    corners.y = (cy - hh) * inv_feat;
    corners.z = (cx + hw) * inv_feat;
    corners.w = (cy + hh) * inv_feat;

    bool m = best > THRESHOLD;
    box_out[i]   = m ? corners : make_float4(0.f, 0.f, 0.f, 0.f);
    probs_out[i] = m ? best : 0.0f;
    cls_out[i]   = (float)bidx;
}

extern "C" void kernel_launch(void* const* d_in, const int* in_sizes, int n_in,
                              void* d_out, int out_size)
{
    const float4*   box    = (const float4*)d_in[0];
    const float*    conf   = (const float*)d_in[1];
    const float4*   score4 = (const float4*)d_in[2];
    const float4*   prior  = (const float4*)d_in[3];
    const unsigned* feat   = (const unsigned*)d_in[4];

    int n_boxes   = in_sizes[1];       // N*HW*A
    int prior_mod = in_sizes[3] / 4;   // HW*A

    float* out       = (float*)d_out;
    float4* box_out  = (float4*)out;
    float*  probs    = out + (size_t)n_boxes * 4;
    float*  cls      = out + (size_t)n_boxes * 5;

    int blocks = (n_boxes + TB - 1) / TB;
    detector_kernel<<<blocks, TB>>>(box, conf, score4, prior, feat,
                                    box_out, probs, cls,
                                    n_boxes, prior_mod);
}